// round 3
// baseline (speedup 1.0000x reference)
#include <cuda_runtime.h>
#include <cuda_bf16.h>
#include <cstdint>

// Problem constants
#define B_   2
#define T_   2048
#define D_   1024
#define H_   16
#define HD_  64
#define M_TOT (B_ * T_)          // 4096 rows

// Scratch (alloc-free rule: __device__ globals)
__device__ float g_qkv[(size_t)B_ * T_ * 3 * D_];   // [B,T,3D]  ~50 MB
__device__ float g_att[(size_t)B_ * T_ * D_];       // [B,T,D]   ~33 MB

// ---------------------------------------------------------------------------
// GEMM: C[M,N] = A[M,K] @ W[N,K]^T   (A row-major, W row-major [out,in])
// 64x64 block tile, 256 threads, 4x4 microtile per thread, BK=16
// ---------------------------------------------------------------------------
__global__ void __launch_bounds__(256) gemm_nt_kernel(
    const float* __restrict__ A, const float* __restrict__ W,
    float* __restrict__ C, int M, int N, int K)
{
    __shared__ float As[16][68];
    __shared__ float Bs[16][68];

    const int tid = threadIdx.x;
    const int m0 = blockIdx.y * 64;
    const int n0 = blockIdx.x * 64;

    const int lrow = tid >> 2;          // 0..63
    const int lk   = (tid & 3) * 4;     // 0,4,8,12

    const int tx = tid & 15;            // 0..15  -> n microtile
    const int ty = tid >> 4;            // 0..15  -> m microtile

    float acc[4][4] = {};

    const float* Ap = A + (size_t)(m0 + lrow) * K + lk;
    const float* Wp = W + (size_t)(n0 + lrow) * K + lk;

    for (int k0 = 0; k0 < K; k0 += 16) {
        float4 av = *(const float4*)(Ap + k0);
        float4 bv = *(const float4*)(Wp + k0);
        As[lk + 0][lrow] = av.x; As[lk + 1][lrow] = av.y;
        As[lk + 2][lrow] = av.z; As[lk + 3][lrow] = av.w;
        Bs[lk + 0][lrow] = bv.x; Bs[lk + 1][lrow] = bv.y;
        Bs[lk + 2][lrow] = bv.z; Bs[lk + 3][lrow] = bv.w;
        __syncthreads();

        #pragma unroll
        for (int kk = 0; kk < 16; kk++) {
            float4 a = *(const float4*)&As[kk][ty * 4];
            float4 b = *(const float4*)&Bs[kk][tx * 4];
            acc[0][0] += a.x * b.x; acc[0][1] += a.x * b.y;
            acc[0][2] += a.x * b.z; acc[0][3] += a.x * b.w;
            acc[1][0] += a.y * b.x; acc[1][1] += a.y * b.y;
            acc[1][2] += a.y * b.z; acc[1][3] += a.y * b.w;
            acc[2][0] += a.z * b.x; acc[2][1] += a.z * b.y;
            acc[2][2] += a.z * b.z; acc[2][3] += a.z * b.w;
            acc[3][0] += a.w * b.x; acc[3][1] += a.w * b.y;
            acc[3][2] += a.w * b.z; acc[3][3] += a.w * b.w;
        }
        __syncthreads();
    }

    #pragma unroll
    for (int i = 0; i < 4; i++) {
        float4 o = make_float4(acc[i][0], acc[i][1], acc[i][2], acc[i][3]);
        *(float4*)&C[(size_t)(m0 + ty * 4 + i) * N + n0 + tx * 4] = o;
    }
}

// ---------------------------------------------------------------------------
// Flash-style causal attention.
// Grid: (T/64, H, B). Block: 64 threads; thread i owns query row q0+i.
// K/V tiles of 64 keys live in shared; online softmax in registers.
// qkv layout: [B, T, 3D]; q at +0, k at +D, v at +2D, head offset h*HD.
// ---------------------------------------------------------------------------
__global__ void __launch_bounds__(64) attn_kernel(
    const float* __restrict__ qkv, float* __restrict__ out)
{
    __shared__ float Ks[64][64];
    __shared__ float Vs[64][64];
    __shared__ float Ssh[64][64];   // indexed [j][tid] -> conflict-free

    const int qt  = blockIdx.x;
    const int h   = blockIdx.y;
    const int b   = blockIdx.z;
    const int tid = threadIdx.x;

    const int qi = qt * 64 + tid;                 // global query index
    const float scale = 0.125f;                   // 64^-0.5

    // load this thread's query row into registers
    const float* qrow = qkv + ((size_t)(b * T_ + qi)) * (3 * D_) + h * HD_;
    float q[64];
    #pragma unroll
    for (int d4 = 0; d4 < 16; d4++) {
        float4 v = *(const float4*)(qrow + d4 * 4);
        q[d4 * 4 + 0] = v.x; q[d4 * 4 + 1] = v.y;
        q[d4 * 4 + 2] = v.z; q[d4 * 4 + 3] = v.w;
    }

    float acc[64];
    #pragma unroll
    for (int d = 0; d < 64; d++) acc[d] = 0.f;
    float m = -1e30f, l = 0.f;

    const int lrow = tid >> 4;          // 0..3
    const int lcol = (tid & 15) * 4;    // 0..60

    for (int kt = 0; kt <= qt; kt++) {
        const int k0 = kt * 64;
        // cooperative coalesced load of K/V tile (64 keys x 64 dims)
        for (int rr = 0; rr < 64; rr += 4) {
            const int krow = k0 + rr + lrow;
            const float* kp = qkv + ((size_t)(b * T_ + krow)) * (3 * D_)
                              + D_ + h * HD_ + lcol;
            float4 kv = *(const float4*)kp;
            float4 vv = *(const float4*)(kp + D_);
            *(float4*)&Ks[rr + lrow][lcol] = kv;
            *(float4*)&Vs[rr + lrow][lcol] = vv;
        }
        __syncthreads();

        // scores for this thread's query against 64 keys
        float smax = -1e30f;
        const bool diag = (kt == qt);
        for (int j = 0; j < 64; j++) {
            float s = 0.f;
            #pragma unroll
            for (int d4 = 0; d4 < 16; d4++) {
                float4 kk = *(const float4*)&Ks[j][d4 * 4];
                s += q[d4 * 4 + 0] * kk.x + q[d4 * 4 + 1] * kk.y
                   + q[d4 * 4 + 2] * kk.z + q[d4 * 4 + 3] * kk.w;
            }
            s *= scale;
            if (diag && j > tid) s = -1e30f;
            Ssh[j][tid] = s;
            smax = fmaxf(smax, s);
        }

        const float mnew = fmaxf(m, smax);
        const float corr = __expf(m - mnew);
        l *= corr;
        #pragma unroll
        for (int d = 0; d < 64; d++) acc[d] *= corr;

        for (int j = 0; j < 64; j++) {
            float p = __expf(Ssh[j][tid] - mnew);
            l += p;
            #pragma unroll
            for (int d4 = 0; d4 < 16; d4++) {
                float4 vv = *(const float4*)&Vs[j][d4 * 4];
                acc[d4 * 4 + 0] += p * vv.x;
                acc[d4 * 4 + 1] += p * vv.y;
                acc[d4 * 4 + 2] += p * vv.z;
                acc[d4 * 4 + 3] += p * vv.w;
            }
        }
        m = mnew;
        __syncthreads();
    }

    const float inv = 1.f / l;
    float* orow = out + ((size_t)(b * T_ + qi)) * D_ + h * HD_;
    #pragma unroll
    for (int d4 = 0; d4 < 16; d4++) {
        float4 o = make_float4(acc[d4 * 4 + 0] * inv, acc[d4 * 4 + 1] * inv,
                               acc[d4 * 4 + 2] * inv, acc[d4 * 4 + 3] * inv);
        *(float4*)(orow + d4 * 4) = o;
    }
}

// ---------------------------------------------------------------------------
extern "C" void kernel_launch(void* const* d_in, const int* in_sizes, int n_in,
                              void* d_out, int out_size)
{
    (void)in_sizes; (void)n_in; (void)out_size;
    const float* x     = (const float*)d_in[0];   // [B,T,D]
    const float* Wqkv  = (const float*)d_in[1];   // [3D, D]
    const float* Wout  = (const float*)d_in[2];   // [D, D]
    float* out = (float*)d_out;                   // [B,T,D]

    float* qkv = nullptr;
    float* att = nullptr;
    cudaGetSymbolAddress((void**)&qkv, g_qkv);
    cudaGetSymbolAddress((void**)&att, g_att);

    // 1) qkv = x @ Wqkv^T   : M=4096, N=3072, K=1024
    {
        dim3 grid(3 * D_ / 64, M_TOT / 64);
        gemm_nt_kernel<<<grid, 256>>>(x, Wqkv, qkv, M_TOT, 3 * D_, D_);
    }
    // 2) causal flash attention -> att [B,T,D]
    {
        dim3 grid(T_ / 64, H_, B_);
        attn_kernel<<<grid, 64>>>(qkv, att);
    }
    // 3) out = att @ Wout^T : M=4096, N=1024, K=1024
    {
        dim3 grid(D_ / 64, M_TOT / 64);
        gemm_nt_kernel<<<grid, 256>>>(att, Wout, out, M_TOT, D_, D_);
    }
}

// round 5
// speedup vs baseline: 3.5052x; 3.5052x over previous
#include <cuda_runtime.h>
#include <cuda_bf16.h>
#include <cstdint>

// Problem constants
#define B_   2
#define T_   2048
#define D_   1024
#define H_   16
#define HD_  64
#define M_TOT (B_ * T_)          // 4096 rows

// Scratch (alloc-free rule: __device__ globals)
__device__ float g_qkv[(size_t)B_ * T_ * 3 * D_];   // [B,T,3D]
__device__ float g_att[(size_t)B_ * T_ * D_];       // [B,T,D]

// ---------------------------------------------------------------------------
// helpers: tf32 convert (round-to-nearest!) and m16n8k8 tf32 mma
// ---------------------------------------------------------------------------
__device__ __forceinline__ uint32_t f2tf(float x) {
    uint32_t u; asm("cvt.rna.tf32.f32 %0, %1;" : "=r"(u) : "f"(x)); return u;
}
__device__ __forceinline__ void mma_tf32(float* c, const uint32_t* a,
                                         uint32_t b0, uint32_t b1) {
    asm volatile(
        "mma.sync.aligned.m16n8k8.row.col.f32.tf32.tf32.f32 "
        "{%0,%1,%2,%3}, {%4,%5,%6,%7}, {%8,%9}, {%0,%1,%2,%3};\n"
        : "+f"(c[0]), "+f"(c[1]), "+f"(c[2]), "+f"(c[3])
        : "r"(a[0]), "r"(a[1]), "r"(a[2]), "r"(a[3]), "r"(b0), "r"(b1));
}

// ---------------------------------------------------------------------------
// TF32 tensor-core GEMM: C[M,N] = A[M,K] @ W[N,K]^T
// Block tile 128x64, 4 warps (2M x 2N), warp tile 64x32, BK=32.
// Smem pitch 36 -> fragment LDS bank pattern (4g+t) mod 32 = conflict-free.
// ---------------------------------------------------------------------------
#define BM 128
#define BN 64
#define BK 32

__global__ void __launch_bounds__(128) gemm_nt_tf32(
    const float* __restrict__ A, const float* __restrict__ W,
    float* __restrict__ C, int M, int N, int K)
{
    __shared__ uint32_t As[BM][BK + 4];
    __shared__ uint32_t Ws[BN][BK + 4];

    const int tid  = threadIdx.x;
    const int warp = tid >> 5;
    const int lane = tid & 31;
    const int g = lane >> 2;            // 0..7
    const int t = lane & 3;             // 0..3
    const int wm = (warp >> 1) * 64;    // 0 or 64
    const int wn = (warp & 1) * 32;     // 0 or 32

    const int m0 = blockIdx.y * BM;
    const int n0 = blockIdx.x * BN;

    // loader mapping: r0 = tid/8, c4 = tid%8 (float4 column), rows step by 16
    const int r0 = tid >> 3;
    const int c4 = tid & 7;

    const float* pA = A + (size_t)(m0 + r0) * K + c4 * 4;
    const float* pW = W + (size_t)(n0 + r0) * K + c4 * 4;

    float acc[4][4][4] = {};
    float4 ra[8], rw[4];

    // prologue: fetch tile 0
    #pragma unroll
    for (int e = 0; e < 8; e++) ra[e] = *(const float4*)(pA + (size_t)e * 16 * K);
    #pragma unroll
    for (int e = 0; e < 4; e++) rw[e] = *(const float4*)(pW + (size_t)e * 16 * K);

    for (int k0 = 0; k0 < K; k0 += BK) {
        // store (convert to tf32) into smem
        #pragma unroll
        for (int e = 0; e < 8; e++) {
            int r = r0 + 16 * e;
            As[r][c4 * 4 + 0] = f2tf(ra[e].x);
            As[r][c4 * 4 + 1] = f2tf(ra[e].y);
            As[r][c4 * 4 + 2] = f2tf(ra[e].z);
            As[r][c4 * 4 + 3] = f2tf(ra[e].w);
        }
        #pragma unroll
        for (int e = 0; e < 4; e++) {
            int r = r0 + 16 * e;
            Ws[r][c4 * 4 + 0] = f2tf(rw[e].x);
            Ws[r][c4 * 4 + 1] = f2tf(rw[e].y);
            Ws[r][c4 * 4 + 2] = f2tf(rw[e].z);
            Ws[r][c4 * 4 + 3] = f2tf(rw[e].w);
        }
        __syncthreads();

        // prefetch next tile while computing
        if (k0 + BK < K) {
            #pragma unroll
            for (int e = 0; e < 8; e++)
                ra[e] = *(const float4*)(pA + (k0 + BK) + (size_t)e * 16 * K);
            #pragma unroll
            for (int e = 0; e < 4; e++)
                rw[e] = *(const float4*)(pW + (k0 + BK) + (size_t)e * 16 * K);
        }

        #pragma unroll
        for (int ks = 0; ks < 4; ks++) {
            const int k = ks * 8;
            uint32_t af[4][4];
            #pragma unroll
            for (int mi = 0; mi < 4; mi++) {
                int r = wm + mi * 16 + g;
                af[mi][0] = As[r][k + t];
                af[mi][1] = As[r + 8][k + t];
                af[mi][2] = As[r][k + t + 4];
                af[mi][3] = As[r + 8][k + t + 4];
            }
            #pragma unroll
            for (int ni = 0; ni < 4; ni++) {
                uint32_t b0 = Ws[wn + ni * 8 + g][k + t];
                uint32_t b1 = Ws[wn + ni * 8 + g][k + t + 4];
                #pragma unroll
                for (int mi = 0; mi < 4; mi++)
                    mma_tf32(acc[mi][ni], af[mi], b0, b1);
            }
        }
        __syncthreads();
    }

    // epilogue
    #pragma unroll
    for (int mi = 0; mi < 4; mi++) {
        int r1 = m0 + wm + mi * 16 + g;
        int r2 = r1 + 8;
        #pragma unroll
        for (int ni = 0; ni < 4; ni++) {
            int c = n0 + wn + ni * 8 + 2 * t;
            *(float2*)&C[(size_t)r1 * N + c] = make_float2(acc[mi][ni][0], acc[mi][ni][1]);
            *(float2*)&C[(size_t)r2 * N + c] = make_float2(acc[mi][ni][2], acc[mi][ni][3]);
        }
    }
}

// ---------------------------------------------------------------------------
// Tensor-core flash attention (causal), tf32 mma.
// Grid: (T/64, H, B). Block: 128 threads = 4 warps. 64 queries per block.
// Warp w owns query rows [w*16, w*16+16). Q fragments register-resident
// (scale folded in). K tile buffer is reused as the P buffer after S is done.
// ---------------------------------------------------------------------------
__global__ void __launch_bounds__(128) attn_tc_kernel(
    const float* __restrict__ qkv, float* __restrict__ out)
{
    __shared__ uint32_t Ss[64][68];    // K tile, then reused for P tile
    __shared__ uint32_t VsT[64][68];   // V transposed: [hd][key]

    const int qt  = blockIdx.x;
    const int h   = blockIdx.y;
    const int b   = blockIdx.z;
    const int tid = threadIdx.x;
    const int warp = tid >> 5;
    const int lane = tid & 31;
    const int g = lane >> 2;
    const int t = lane & 3;

    const int bT   = b * T_;
    const int hoff = h * HD_;
    const int rw1  = warp * 16 + g;       // within-tile query row 1
    const int rw2  = rw1 + 8;             // within-tile query row 2
    const float scale = 0.125f;           // HD^-0.5

    // loader mapping for 64x64 tiles: r0 = tid/16 (0..7), c4 = tid%16
    const int r0 = tid >> 4;
    const int c4 = tid & 15;

    // Q fragments (scale folded into tf32 conversion)
    const float* q1 = qkv + ((size_t)(bT + qt * 64 + rw1)) * (3 * D_) + hoff;
    const float* q2 = q1 + (size_t)8 * 3 * D_;
    uint32_t qa[8][4];
    #pragma unroll
    for (int ks = 0; ks < 8; ks++) {
        const int k = ks * 8;
        qa[ks][0] = f2tf(scale * q1[k + t]);
        qa[ks][1] = f2tf(scale * q2[k + t]);
        qa[ks][2] = f2tf(scale * q1[k + t + 4]);
        qa[ks][3] = f2tf(scale * q2[k + t + 4]);
    }

    float oa[8][4] = {};
    float m1 = -1e30f, m2 = -1e30f, l1 = 0.f, l2 = 0.f;

    for (int kt = 0; kt <= qt; kt++) {
        const int k0 = kt * 64;

        // load K into Ss, V transposed into VsT
        #pragma unroll
        for (int e = 0; e < 8; e++) {
            const int key = r0 + 8 * e;
            const float* p = qkv + ((size_t)(bT + k0 + key)) * (3 * D_)
                             + D_ + hoff + c4 * 4;
            float4 kv = *(const float4*)p;
            float4 vv = *(const float4*)(p + D_);
            Ss[key][c4 * 4 + 0] = f2tf(kv.x);
            Ss[key][c4 * 4 + 1] = f2tf(kv.y);
            Ss[key][c4 * 4 + 2] = f2tf(kv.z);
            Ss[key][c4 * 4 + 3] = f2tf(kv.w);
            VsT[c4 * 4 + 0][key] = f2tf(vv.x);
            VsT[c4 * 4 + 1][key] = f2tf(vv.y);
            VsT[c4 * 4 + 2][key] = f2tf(vv.z);
            VsT[c4 * 4 + 3][key] = f2tf(vv.w);
        }
        __syncthreads();

        // S = (scaled Q) @ K^T   (64x64, n = keys)
        float sa[8][4] = {};
        #pragma unroll
        for (int ks = 0; ks < 8; ks++) {
            const int k = ks * 8;
            #pragma unroll
            for (int ni = 0; ni < 8; ni++) {
                uint32_t b0 = Ss[ni * 8 + g][k + t];
                uint32_t b1 = Ss[ni * 8 + g][k + t + 4];
                mma_tf32(sa[ni], qa[ks], b0, b1);
            }
        }

        // causal mask (diagonal tile only)
        if (kt == qt) {
            #pragma unroll
            for (int ni = 0; ni < 8; ni++) {
                const int c0 = ni * 8 + 2 * t, c1 = c0 + 1;
                if (c0 > rw1) sa[ni][0] = -1e30f;
                if (c1 > rw1) sa[ni][1] = -1e30f;
                if (c0 > rw2) sa[ni][2] = -1e30f;
                if (c1 > rw2) sa[ni][3] = -1e30f;
            }
        }

        // row max (thread-local, then reduce across the quad: lanes t^1, t^2)
        float mx1 = -1e30f, mx2 = -1e30f;
        #pragma unroll
        for (int ni = 0; ni < 8; ni++) {
            mx1 = fmaxf(mx1, fmaxf(sa[ni][0], sa[ni][1]));
            mx2 = fmaxf(mx2, fmaxf(sa[ni][2], sa[ni][3]));
        }
        mx1 = fmaxf(mx1, __shfl_xor_sync(0xffffffffu, mx1, 1));
        mx1 = fmaxf(mx1, __shfl_xor_sync(0xffffffffu, mx1, 2));
        mx2 = fmaxf(mx2, __shfl_xor_sync(0xffffffffu, mx2, 1));
        mx2 = fmaxf(mx2, __shfl_xor_sync(0xffffffffu, mx2, 2));

        const float mn1 = fmaxf(m1, mx1);
        const float mn2 = fmaxf(m2, mx2);
        const float corr1 = __expf(m1 - mn1);
        const float corr2 = __expf(m2 - mn2);

        float rs1 = 0.f, rs2 = 0.f;
        #pragma unroll
        for (int ni = 0; ni < 8; ni++) {
            sa[ni][0] = __expf(sa[ni][0] - mn1);
            sa[ni][1] = __expf(sa[ni][1] - mn1);
            sa[ni][2] = __expf(sa[ni][2] - mn2);
            sa[ni][3] = __expf(sa[ni][3] - mn2);
            rs1 += sa[ni][0] + sa[ni][1];
            rs2 += sa[ni][2] + sa[ni][3];
        }
        rs1 += __shfl_xor_sync(0xffffffffu, rs1, 1);
        rs1 += __shfl_xor_sync(0xffffffffu, rs1, 2);
        rs2 += __shfl_xor_sync(0xffffffffu, rs2, 1);
        rs2 += __shfl_xor_sync(0xffffffffu, rs2, 2);
        l1 = l1 * corr1 + rs1;
        l2 = l2 * corr2 + rs2;
        m1 = mn1; m2 = mn2;

        // rescale O accumulators
        #pragma unroll
        for (int ni = 0; ni < 8; ni++) {
            oa[ni][0] *= corr1; oa[ni][1] *= corr1;
            oa[ni][2] *= corr2; oa[ni][3] *= corr2;
        }

        // write P into the K buffer (all warps done reading K: barrier first)
        __syncthreads();
        #pragma unroll
        for (int ni = 0; ni < 8; ni++) {
            const int c = ni * 8 + 2 * t;
            Ss[rw1][c]     = f2tf(sa[ni][0]);
            Ss[rw1][c + 1] = f2tf(sa[ni][1]);
            Ss[rw2][c]     = f2tf(sa[ni][2]);
            Ss[rw2][c + 1] = f2tf(sa[ni][3]);
        }
        __syncwarp();   // each warp reads only its own P rows

        // O += P @ V  (k = keys, n = hd)
        #pragma unroll
        for (int ks = 0; ks < 8; ks++) {
            const int k = ks * 8;
            uint32_t pa[4];
            pa[0] = Ss[rw1][k + t];
            pa[1] = Ss[rw2][k + t];
            pa[2] = Ss[rw1][k + t + 4];
            pa[3] = Ss[rw2][k + t + 4];
            #pragma unroll
            for (int ni = 0; ni < 8; ni++) {
                uint32_t b0 = VsT[ni * 8 + g][k + t];
                uint32_t b1 = VsT[ni * 8 + g][k + t + 4];
                mma_tf32(oa[ni], pa, b0, b1);
            }
        }
        __syncthreads();   // protect Ss/VsT before next tile's loads
    }

    // normalize + write
    const float inv1 = 1.f / l1;
    const float inv2 = 1.f / l2;
    float* o1 = out + ((size_t)(bT + qt * 64 + rw1)) * D_ + hoff;
    float* o2 = o1 + (size_t)8 * D_;
    #pragma unroll
    for (int ni = 0; ni < 8; ni++) {
        const int c = ni * 8 + 2 * t;
        *(float2*)(o1 + c) = make_float2(oa[ni][0] * inv1, oa[ni][1] * inv1);
        *(float2*)(o2 + c) = make_float2(oa[ni][2] * inv2, oa[ni][3] * inv2);
    }
}

// ---------------------------------------------------------------------------
extern "C" void kernel_launch(void* const* d_in, const int* in_sizes, int n_in,
                              void* d_out, int out_size)
{
    (void)in_sizes; (void)n_in; (void)out_size;
    const float* x     = (const float*)d_in[0];   // [B,T,D]
    const float* Wqkv  = (const float*)d_in[1];   // [3D, D]
    const float* Wout  = (const float*)d_in[2];   // [D, D]
    float* out = (float*)d_out;                   // [B,T,D]

    float* qkv = nullptr;
    float* att = nullptr;
    cudaGetSymbolAddress((void**)&qkv, g_qkv);
    cudaGetSymbolAddress((void**)&att, g_att);

    // 1) qkv = x @ Wqkv^T : M=4096, N=3072, K=1024
    {
        dim3 grid(3 * D_ / BN, M_TOT / BM);
        gemm_nt_tf32<<<grid, 128>>>(x, Wqkv, qkv, M_TOT, 3 * D_, D_);
    }
    // 2) causal flash attention (tensor cores) -> att [B,T,D]
    {
        dim3 grid(T_ / 64, H_, B_);
        attn_tc_kernel<<<grid, 128>>>(qkv, att);
    }
    // 3) out = att @ Wout^T : M=4096, N=1024, K=1024
    {
        dim3 grid(D_ / BN, M_TOT / BM);
        gemm_nt_tf32<<<grid, 128>>>(att, Wout, out, M_TOT, D_, D_);
    }
}

// round 9
// speedup vs baseline: 3.5171x; 1.0034x over previous
#include <cuda_runtime.h>
#include <cuda_bf16.h>
#include <cstdint>

// Problem constants
#define B_   2
#define T_   2048
#define D_   1024
#define H_   16
#define HD_  64
#define M_TOT (B_ * T_)          // 4096 rows

// Scratch (alloc-free rule: __device__ globals). All tf32 bit patterns.
__device__ uint32_t g_x_tf [(size_t)M_TOT * D_];          // x as tf32
__device__ uint32_t g_wq_tf[(size_t)3 * D_ * D_];         // W_qkv as tf32
__device__ uint32_t g_wo_tf[(size_t)D_ * D_];             // W_out as tf32
__device__ uint32_t g_qkv  [(size_t)M_TOT * 3 * D_];      // qkv as tf32
__device__ uint32_t g_att  [(size_t)M_TOT * D_];          // attn out as tf32

// ---------------------------------------------------------------------------
// helpers
// ---------------------------------------------------------------------------
__device__ __forceinline__ uint32_t f2tf(float x) {
    uint32_t u; asm("cvt.rna.tf32.f32 %0, %1;" : "=r"(u) : "f"(x)); return u;
}
__device__ __forceinline__ void mma_tf32(float* c, const uint32_t* a,
                                         uint32_t b0, uint32_t b1) {
    asm volatile(
        "mma.sync.aligned.m16n8k8.row.col.f32.tf32.tf32.f32 "
        "{%0,%1,%2,%3}, {%4,%5,%6,%7}, {%8,%9}, {%0,%1,%2,%3};\n"
        : "+f"(c[0]), "+f"(c[1]), "+f"(c[2]), "+f"(c[3])
        : "r"(a[0]), "r"(a[1]), "r"(a[2]), "r"(a[3]), "r"(b0), "r"(b1));
}
#define CP_ASYNC16(dst, src) \
    asm volatile("cp.async.cg.shared.global [%0], [%1], 16;\n" :: "r"(dst), "l"(src))
#define CP_COMMIT() asm volatile("cp.async.commit_group;\n" ::)
#define CP_WAIT(n)  asm volatile("cp.async.wait_group %0;\n" :: "n"(n))

// ---------------------------------------------------------------------------
// elementwise fp32 -> tf32 bits
// ---------------------------------------------------------------------------
__global__ void __launch_bounds__(256) conv_tf32_kernel(
    const float* __restrict__ in, uint32_t* __restrict__ out, int n)
{
    int i = (blockIdx.x * 256 + threadIdx.x) * 4;
    if (i < n) {
        float4 v = *(const float4*)(in + i);
        uint4 o = make_uint4(f2tf(v.x), f2tf(v.y), f2tf(v.z), f2tf(v.w));
        *(uint4*)(out + i) = o;
    }
}

// ---------------------------------------------------------------------------
// TF32 GEMM, pre-converted inputs: C[M,N] = A[M,K] @ W[N,K]^T
// 128x128 block, 8 warps (2x4), warp tile 64x32, BK=16, cp.async 2-stage.
// conv_out: 1 -> store tf32 bits; 0 -> store fp32.
// ---------------------------------------------------------------------------
#define BM 128
#define BN 128
#define BK 16
#define BKP 20

__global__ void __launch_bounds__(256) gemm_tt32(
    const uint32_t* __restrict__ A, const uint32_t* __restrict__ W,
    void* __restrict__ Cout, int M, int N, int K, int conv_out)
{
    __shared__ uint32_t As[2][BM][BKP];
    __shared__ uint32_t Bs[2][BN][BKP];

    const int tid  = threadIdx.x;
    const int warp = tid >> 5;
    const int lane = tid & 31;
    const int g = lane >> 2;
    const int t = lane & 3;
    const int wm = (warp >> 2) * 64;     // 0, 64
    const int wn = (warp & 3) * 32;      // 0..96

    const int m0 = blockIdx.y * BM;
    const int n0 = blockIdx.x * BN;

    const int lr = tid >> 2;             // 0..63
    const int lc = (tid & 3) * 4;        // 0,4,8,12

    const uint32_t* pA = A + (size_t)(m0 + lr) * K + lc;
    const uint32_t* pW = W + (size_t)(n0 + lr) * K + lc;

    uint32_t sA0 = (uint32_t)__cvta_generic_to_shared(&As[0][lr][lc]);
    uint32_t sA1 = (uint32_t)__cvta_generic_to_shared(&As[0][lr + 64][lc]);
    uint32_t sB0 = (uint32_t)__cvta_generic_to_shared(&Bs[0][lr][lc]);
    uint32_t sB1 = (uint32_t)__cvta_generic_to_shared(&Bs[0][lr + 64][lc]);
    const uint32_t stg = (uint32_t)(BM * BKP * 4);   // bytes per stage

    float acc[4][4][4] = {};

    const int KT = K / BK;

    // prologue: stage 0
    CP_ASYNC16(sA0, pA);
    CP_ASYNC16(sA1, pA + (size_t)64 * K);
    CP_ASYNC16(sB0, pW);
    CP_ASYNC16(sB1, pW + (size_t)64 * K);
    CP_COMMIT();

    for (int kt = 0; kt < KT; kt++) {
        const int buf = kt & 1;
        if (kt + 1 < KT) {
            const int nb = (kt + 1) & 1;
            const int ko = (kt + 1) * BK;
            CP_ASYNC16(sA0 + nb * stg, pA + ko);
            CP_ASYNC16(sA1 + nb * stg, pA + ko + (size_t)64 * K);
            CP_ASYNC16(sB0 + nb * stg, pW + ko);
            CP_ASYNC16(sB1 + nb * stg, pW + ko + (size_t)64 * K);
            CP_COMMIT();
            CP_WAIT(1);
        } else {
            CP_WAIT(0);
        }
        __syncthreads();

        #pragma unroll
        for (int ks = 0; ks < 2; ks++) {
            const int k = ks * 8;
            uint32_t af[4][4];
            #pragma unroll
            for (int mi = 0; mi < 4; mi++) {
                const int r = wm + mi * 16 + g;
                af[mi][0] = As[buf][r][k + t];
                af[mi][1] = As[buf][r + 8][k + t];
                af[mi][2] = As[buf][r][k + t + 4];
                af[mi][3] = As[buf][r + 8][k + t + 4];
            }
            #pragma unroll
            for (int ni = 0; ni < 4; ni++) {
                const int rb = wn + ni * 8 + g;
                uint32_t b0 = Bs[buf][rb][k + t];
                uint32_t b1 = Bs[buf][rb][k + t + 4];
                #pragma unroll
                for (int mi = 0; mi < 4; mi++)
                    mma_tf32(acc[mi][ni], af[mi], b0, b1);
            }
        }
        __syncthreads();
    }

    // epilogue
    if (conv_out) {
        uint32_t* C = (uint32_t*)Cout;
        #pragma unroll
        for (int mi = 0; mi < 4; mi++) {
            const int r1 = m0 + wm + mi * 16 + g;
            const int r2 = r1 + 8;
            #pragma unroll
            for (int ni = 0; ni < 4; ni++) {
                const int c = n0 + wn + ni * 8 + 2 * t;
                *(uint2*)&C[(size_t)r1 * N + c] =
                    make_uint2(f2tf(acc[mi][ni][0]), f2tf(acc[mi][ni][1]));
                *(uint2*)&C[(size_t)r2 * N + c] =
                    make_uint2(f2tf(acc[mi][ni][2]), f2tf(acc[mi][ni][3]));
            }
        }
    } else {
        float* C = (float*)Cout;
        #pragma unroll
        for (int mi = 0; mi < 4; mi++) {
            const int r1 = m0 + wm + mi * 16 + g;
            const int r2 = r1 + 8;
            #pragma unroll
            for (int ni = 0; ni < 4; ni++) {
                const int c = n0 + wn + ni * 8 + 2 * t;
                *(float2*)&C[(size_t)r1 * N + c] =
                    make_float2(acc[mi][ni][0], acc[mi][ni][1]);
                *(float2*)&C[(size_t)r2 * N + c] =
                    make_float2(acc[mi][ni][2], acc[mi][ni][3]);
            }
        }
    }
}

// ---------------------------------------------------------------------------
// Tensor-core flash attention (causal), tf32 inputs (pre-converted bits).
// Grid: (T/128, H, B), 256 threads = 8 warps, 128 queries/block.
// Warp w owns query rows [w*16, w*16+16). P never touches smem: S-fragment
// (C layout) is converted to A layout via quad shuffles.
// Heavy blocks (high qt) are launched first: qt = gridDim.x-1-blockIdx.x.
// ---------------------------------------------------------------------------
#define AQ 128

__global__ void __launch_bounds__(256) attn_tc_kernel(
    const uint32_t* __restrict__ qkv, uint32_t* __restrict__ out)
{
    __shared__ uint32_t Ks[64][68];
    __shared__ uint32_t VsT[64][68];

    const int qt  = gridDim.x - 1 - blockIdx.x;  // heavy first
    const int h   = blockIdx.y;
    const int b   = blockIdx.z;
    const int tid = threadIdx.x;
    const int warp = tid >> 5;
    const int lane = tid & 31;
    const int g = lane >> 2;
    const int t = lane & 3;

    const int bT   = b * T_;
    const int hoff = h * HD_;
    const int rw1  = warp * 16 + g;    // 0..127
    const int rw2  = rw1 + 8;

    // loader mapping: row = tid/4 (0..63), base col chunk = (tid%4)*4
    const int lr = tid >> 2;
    const int lc = (tid & 3) * 4;

    // Q fragments; x0.125 scale is exponent-exact on tf32 values
    const uint32_t* q1 = qkv + ((size_t)(bT + qt * AQ + rw1)) * (3 * D_) + hoff;
    const uint32_t* q2 = q1 + (size_t)8 * 3 * D_;
    uint32_t qa[8][4];
    #pragma unroll
    for (int ks = 0; ks < 8; ks++) {
        const int k = ks * 8;
        qa[ks][0] = __float_as_uint(0.125f * __uint_as_float(q1[k + t]));
        qa[ks][1] = __float_as_uint(0.125f * __uint_as_float(q2[k + t]));
        qa[ks][2] = __float_as_uint(0.125f * __uint_as_float(q1[k + t + 4]));
        qa[ks][3] = __float_as_uint(0.125f * __uint_as_float(q2[k + t + 4]));
    }

    float oa[8][4] = {};
    float m1 = -1e30f, m2 = -1e30f, l1 = 0.f, l2 = 0.f;

    const int ktmax = 2 * qt + 1;
    for (int kt = 0; kt <= ktmax; kt++) {
        const int k0 = kt * 64;

        // load K tile + V tile (transposed); raw tf32 bits, no conversion
        {
            const uint32_t* base = qkv + ((size_t)(bT + k0 + lr)) * (3 * D_) + hoff;
            #pragma unroll
            for (int j = 0; j < 4; j++) {
                const int c = lc + j * 16;
                uint4 kv = *(const uint4*)(base + D_ + c);
                uint4 vv = *(const uint4*)(base + 2 * D_ + c);
                *(uint4*)&Ks[lr][c] = kv;
                VsT[c + 0][lr] = vv.x;
                VsT[c + 1][lr] = vv.y;
                VsT[c + 2][lr] = vv.z;
                VsT[c + 3][lr] = vv.w;
            }
        }
        __syncthreads();

        // S = (scaled Q) @ K^T
        float sa[8][4] = {};
        #pragma unroll
        for (int ks = 0; ks < 8; ks++) {
            const int k = ks * 8;
            #pragma unroll
            for (int ni = 0; ni < 8; ni++) {
                uint32_t b0 = Ks[ni * 8 + g][k + t];
                uint32_t b1 = Ks[ni * 8 + g][k + t + 4];
                mma_tf32(sa[ni], qa[ks], b0, b1);
            }
        }

        // causal mask (last two key tiles only)
        if (kt >= 2 * qt) {
            const int off = (kt - 2 * qt) * 64;
            #pragma unroll
            for (int ni = 0; ni < 8; ni++) {
                const int c0 = off + ni * 8 + 2 * t, c1 = c0 + 1;
                if (c0 > rw1) sa[ni][0] = -1e30f;
                if (c1 > rw1) sa[ni][1] = -1e30f;
                if (c0 > rw2) sa[ni][2] = -1e30f;
                if (c1 > rw2) sa[ni][3] = -1e30f;
            }
        }

        // online softmax (quad reductions)
        float mx1 = -1e30f, mx2 = -1e30f;
        #pragma unroll
        for (int ni = 0; ni < 8; ni++) {
            mx1 = fmaxf(mx1, fmaxf(sa[ni][0], sa[ni][1]));
            mx2 = fmaxf(mx2, fmaxf(sa[ni][2], sa[ni][3]));
        }
        mx1 = fmaxf(mx1, __shfl_xor_sync(0xffffffffu, mx1, 1));
        mx1 = fmaxf(mx1, __shfl_xor_sync(0xffffffffu, mx1, 2));
        mx2 = fmaxf(mx2, __shfl_xor_sync(0xffffffffu, mx2, 1));
        mx2 = fmaxf(mx2, __shfl_xor_sync(0xffffffffu, mx2, 2));

        const float mn1 = fmaxf(m1, mx1);
        const float mn2 = fmaxf(m2, mx2);
        const float corr1 = __expf(m1 - mn1);
        const float corr2 = __expf(m2 - mn2);

        float rs1 = 0.f, rs2 = 0.f;
        #pragma unroll
        for (int ni = 0; ni < 8; ni++) {
            sa[ni][0] = __expf(sa[ni][0] - mn1);
            sa[ni][1] = __expf(sa[ni][1] - mn1);
            sa[ni][2] = __expf(sa[ni][2] - mn2);
            sa[ni][3] = __expf(sa[ni][3] - mn2);
            rs1 += sa[ni][0] + sa[ni][1];
            rs2 += sa[ni][2] + sa[ni][3];
        }
        rs1 += __shfl_xor_sync(0xffffffffu, rs1, 1);
        rs1 += __shfl_xor_sync(0xffffffffu, rs1, 2);
        rs2 += __shfl_xor_sync(0xffffffffu, rs2, 1);
        rs2 += __shfl_xor_sync(0xffffffffu, rs2, 2);
        l1 = l1 * corr1 + rs1;
        l2 = l2 * corr2 + rs2;
        m1 = mn1; m2 = mn2;

        #pragma unroll
        for (int ni = 0; ni < 8; ni++) {
            oa[ni][0] *= corr1; oa[ni][1] *= corr1;
            oa[ni][2] *= corr2; oa[ni][3] *= corr2;
        }

        // O += P @ V. P C-fragment -> A-fragment via quad shuffles.
        // S tile ni == PV k-slice ks. Col c of P is held by lane g*4+(c>>1),
        // element (c&1) for row g, 2+(c&1) for row g+8.
        const int L1 = g * 4 + (t >> 1);
        const int L2 = L1 + 2;
        const bool odd = (t & 1);
        #pragma unroll
        for (int ks = 0; ks < 8; ks++) {
            uint32_t p0 = f2tf(sa[ks][0]);
            uint32_t p1 = f2tf(sa[ks][1]);
            uint32_t p2 = f2tf(sa[ks][2]);
            uint32_t p3 = f2tf(sa[ks][3]);
            uint32_t v0 = __shfl_sync(0xffffffffu, p0, L1);
            uint32_t v1 = __shfl_sync(0xffffffffu, p1, L1);
            uint32_t v2 = __shfl_sync(0xffffffffu, p2, L1);
            uint32_t v3 = __shfl_sync(0xffffffffu, p3, L1);
            uint32_t w0 = __shfl_sync(0xffffffffu, p0, L2);
            uint32_t w1 = __shfl_sync(0xffffffffu, p1, L2);
            uint32_t w2 = __shfl_sync(0xffffffffu, p2, L2);
            uint32_t w3 = __shfl_sync(0xffffffffu, p3, L2);
            uint32_t pa[4];
            pa[0] = odd ? v1 : v0;     // P[g][t]
            pa[1] = odd ? v3 : v2;     // P[g+8][t]
            pa[2] = odd ? w1 : w0;     // P[g][t+4]
            pa[3] = odd ? w3 : w2;     // P[g+8][t+4]

            const int k = ks * 8;
            #pragma unroll
            for (int ni = 0; ni < 8; ni++) {
                uint32_t b0 = VsT[ni * 8 + g][k + t];
                uint32_t b1 = VsT[ni * 8 + g][k + t + 4];
                mma_tf32(oa[ni], pa, b0, b1);
            }
        }
        __syncthreads();   // protect Ks/VsT before next tile's loads
    }

    // normalize + write as tf32 bits (consumed by the tf32 out-proj GEMM)
    const float inv1 = 1.f / l1;
    const float inv2 = 1.f / l2;
    uint32_t* o1 = out + ((size_t)(bT + qt * AQ + rw1)) * D_ + hoff;
    uint32_t* o2 = o1 + (size_t)8 * D_;
    #pragma unroll
    for (int ni = 0; ni < 8; ni++) {
        const int c = ni * 8 + 2 * t;
        *(uint2*)(o1 + c) = make_uint2(f2tf(oa[ni][0] * inv1), f2tf(oa[ni][1] * inv1));
        *(uint2*)(o2 + c) = make_uint2(f2tf(oa[ni][2] * inv2), f2tf(oa[ni][3] * inv2));
    }
}

// ---------------------------------------------------------------------------
extern "C" void kernel_launch(void* const* d_in, const int* in_sizes, int n_in,
                              void* d_out, int out_size)
{
    (void)in_sizes; (void)n_in; (void)out_size;
    const float* x    = (const float*)d_in[0];   // [B,T,D]
    const float* Wqkv = (const float*)d_in[1];   // [3D, D]
    const float* Wout = (const float*)d_in[2];   // [D, D]
    float* out = (float*)d_out;                  // [B,T,D]

    uint32_t *x_tf, *wq_tf, *wo_tf, *qkv, *att;
    cudaGetSymbolAddress((void**)&x_tf,  g_x_tf);
    cudaGetSymbolAddress((void**)&wq_tf, g_wq_tf);
    cudaGetSymbolAddress((void**)&wo_tf, g_wo_tf);
    cudaGetSymbolAddress((void**)&qkv,   g_qkv);
    cudaGetSymbolAddress((void**)&att,   g_att);

    // 0) pre-convert inputs to tf32 bits (once per launch; pure bandwidth)
    {
        const int nx = M_TOT * D_;          // 4.19M
        const int nq = 3 * D_ * D_;         // 3.15M
        const int no = D_ * D_;             // 1.05M
        conv_tf32_kernel<<<nx / 1024, 256>>>(x, x_tf, nx);
        conv_tf32_kernel<<<nq / 1024, 256>>>(Wqkv, wq_tf, nq);
        conv_tf32_kernel<<<no / 1024, 256>>>(Wout, wo_tf, no);
    }
    // 1) qkv = x @ Wqkv^T : M=4096, N=3072, K=1024 (tf32 in, tf32 bits out)
    {
        dim3 grid(3 * D_ / BN, M_TOT / BM);
        gemm_tt32<<<grid, 256>>>(x_tf, wq_tf, qkv, M_TOT, 3 * D_, D_, 1);
    }
    // 2) causal flash attention -> att (tf32 bits)
    {
        dim3 grid(T_ / AQ, H_, B_);
        attn_tc_kernel<<<grid, 256>>>(qkv, att);
    }
    // 3) out = att @ Wout^T : M=4096, N=1024, K=1024 (fp32 out)
    {
        dim3 grid(D_ / BN, M_TOT / BM);
        gemm_tt32<<<grid, 256>>>(att, wo_tf, out, M_TOT, D_, D_, 0);
    }
}